// round 8
// baseline (speedup 1.0000x reference)
#include <cuda_runtime.h>
#include <cuda_bf16.h>

// TransferMatrixMethod: B=256, L=64 (62 interior), W=512.
// Layer matrices [[a, ib],[ic, d]] (real a,b,c,d) closed under multiplication.
//
// ROTATION FORM (R7, verified): state (A, Bt=n*B, C, Dh=-n*D). Per layer with
// r = n_next/n_cur (last r of a chunk = 1/n_last), cpr=cp*r, mspr=-sp*r:
//   A'  = cp*A  + sp*Bt      Bt' = cpr*Bt + mspr*A
//   C'  = cp*C  + sp*Dh      Dh' = cpr*Dh + mspr*C
// Chunk ends in plain form (Bt=B, Dh=-D=Dt).
//
// SCALAR, 1 wavelength per thread, 16384 warps (full occupancy, regs<=32).
// 4-way layer split (identity-padded to 64 layers), combine via lane xor 8
// then xor 16:  Z = L*R:
//   Z_A = LA*RA - LB*RC       Z_B  = LA*RB - LB*RDt
//   Z_C = LC*RA - LDt*RC      Z_Dt = -LDt*RDt + LC*RB
//
// Epilogue: E=A+i*B*nsub, H=D*nsub+i*C, r=(nin*E-H)/(nin*E+H), R=|num|^2/|den|^2.

#define LTOT 64
#define WDIM 512
#define TPB  128

__device__ __forceinline__ void combine_sc(float& A, float& B, float& C, float& Dt,
                                           int xm, bool upper)
{
    const unsigned FULL = 0xffffffffu;
    float pA  = __shfl_xor_sync(FULL, A,  xm);
    float pB  = __shfl_xor_sync(FULL, B,  xm);
    float pC  = __shfl_xor_sync(FULL, C,  xm);
    float pDt = __shfl_xor_sync(FULL, Dt, xm);

    float LA  = upper ? pA  : A;   float RA  = upper ? A  : pA;
    float LB  = upper ? pB  : B;   float RB  = upper ? B  : pB;
    float LC  = upper ? pC  : C;   float RC  = upper ? C  : pC;
    float LDt = upper ? pDt : Dt;  float RDt = upper ? Dt : pDt;

    float zA  = fmaf(-LB,  RC,  LA * RA);
    float zB  = fmaf(-LB,  RDt, LA * RB);
    float zC  = fmaf(-LDt, RC,  LC * RA);
    float zDt = fmaf(-LDt, RDt, LC * RB);
    A = zA; B = zB; C = zC; Dt = zDt;
}

__global__ __launch_bounds__(TPB, 16)
void tmm_kernel(const float* __restrict__ n_layers,
                const float* __restrict__ d_layers,
                const float* __restrict__ wavelengths,
                float* __restrict__ out)
{
    const int b    = blockIdx.x >> 4;        // 0..255
    const int g    = blockIdx.x & 15;        // 16 wavelength groups of 32
    const int t    = threadIdx.x;            // 0..127
    const int lane = t & 31;
    const int wrp  = t >> 5;
    const int h    = lane >> 3;              // layer-split index, 0..3
    const int chain = wrp * 8 + (lane & 7);  // 0..31 in block
    const int w    = g * 32 + chain;         // this thread's wavelength

    // padded layer tables: idx = 17*h + j, j in [0,16); layers 62,63 identity
    __shared__ float2 s_ndr[68];   // {n*d, ratio}
    __shared__ float  s_dh0[4];    // -n_first per chunk
    __shared__ float  s_nin, s_nsub;

    if (t < 64) {
        const int hh = t >> 4, j = t & 15, idx = hh * 17 + j;
        float nv = 1.0f, dv = 0.0f;
        if (t < 62) {
            nv = n_layers[b * LTOT + t + 1];
            dv = d_layers[b * LTOT + t + 1];
        }
        float nn = 1.0f;
        if (j < 15) {
            const int Lp = t + 1;
            nn = (Lp < 62) ? n_layers[b * LTOT + Lp + 1] : 1.0f;
        }
        s_ndr[idx] = make_float2(nv * dv, nn / nv);
        if (j == 0) s_dh0[hh] = -nv;
    }
    if (t == 64) s_nin  = n_layers[b * LTOT];
    if (t == 65) s_nsub = n_layers[b * LTOT + LTOT - 1];
    __syncthreads();

    const float TWO_PI = 6.28318530717958647692f;
    const float k = __fdividef(TWO_PI, wavelengths[w]);

    const int base = h * 17;

    float A  = 1.0f;
    float Bt = 0.0f;
    float C  = 0.0f;
    float Dh = s_dh0[h];      // -n_first

    // prologue: trig + ratio for j = 0
    float2 ndr = s_ndr[base];
    float sp, cp;
    __sincosf(ndr.x * k, &sp, &cp);

    #pragma unroll
    for (int j = 0; j < 16; ++j) {
        const float s = sp, cc = cp, r = ndr.y;

        // ---- prefetch next layer's table + trig (independent stream) ----
        if (j < 15) {
            ndr = s_ndr[base + j + 1];
            __sincosf(ndr.x * k, &sp, &cp);
        }

        // ---- matrix update for layer j ----
        const float cpr  = cc * r;
        const float mspr = -s * r;

        float nA = fmaf(s,    Bt, cc  * A);
        float nB = fmaf(mspr, A,  cpr * Bt);
        float nC = fmaf(s,    Dh, cc  * C);
        float nD = fmaf(mspr, C,  cpr * Dh);
        A = nA; Bt = nB; C = nC; Dh = nD;
    }
    // chunk ends in plain form: Bt = B, Dh = -D = Dt

    combine_sc(A, Bt, C, Dh, 8,  (h & 1) != 0);
    combine_sc(A, Bt, C, Dh, 16, (h & 2) != 0);

    if (h == 0) {
        const float nin  = s_nin;
        const float nsub = s_nsub;
        const float D    = -Dh;

        const float Er = A + 1e-9f;
        const float Ei = Bt * nsub;
        const float Hr = D * nsub;
        const float Hi = C;

        const float numr = fmaf(nin, Er, -Hr);
        const float numi = fmaf(nin, Ei, -Hi);
        const float denr = fmaf(nin, Er,  Hr);
        const float deni = fmaf(nin, Ei,  Hi);

        const float num2 = fmaf(numr, numr, numi * numi);
        const float den2 = fmaf(denr, denr, deni * deni);

        out[b * WDIM + w] = num2 / den2;
    }
}

extern "C" void kernel_launch(void* const* d_in, const int* in_sizes, int n_in,
                              void* d_out, int out_size)
{
    const float* n_layers    = (const float*)d_in[0];  // (256, 64)
    const float* d_layers    = (const float*)d_in[1];  // (256, 64)
    const float* wavelengths = (const float*)d_in[2];  // (512,)
    float* out = (float*)d_out;                        // (256, 512)

    tmm_kernel<<<256 * 16, TPB>>>(n_layers, d_layers, wavelengths, out);
}